// round 16
// baseline (speedup 1.0000x reference)
#include <cuda_runtime.h>
#include <cuda_fp16.h>
#include <cstdint>

// ===========================================================================
// 3x conv3x3 chain via mma.sync.m16n8k16 FP16 (fp32 accum), NHWC half
// intermediates. Round 16 = round-15 champion + L1 relief:
//  - cp.async .cg (no L1 allocation for stage fills; data is read from smem,
//    never from L1 cache -> .ca sector fills were pure overhead on the
//    measured top pipe, l1tex = 76.4%).
//  - both prep kernels merged into one launch.
//  - conv1/2: CTA = 128co x 112pix, 8 warps = 4(m) x 2(n), 2 CTAs/SM.
//  - conv3:   CTA =  64co x 224pix, 8 warps = 2(m) x 4(n), 2 CTAs/SM.
//  - K=64 stages (one tap x 64 contiguous ci), double buffer, one sync/stage,
//    pitch-144 conflict-free smem rows.
// N=16, H=W=224, 64 -> 128 -> 128 -> 64, fp32 NCHW in/out.
// ===========================================================================

#define HW     224
#define PADH   226
#define PADW   256
#define NIMG   16

__device__ __half g_padX [NIMG * PADH * PADW *  64];   // zero-init -> borders stay 0
__device__ __half g_padB1[NIMG * PADH * PADW * 128];
__device__ __half g_padB2[NIMG * PADH * PADW * 128];
__device__ __half g_wt1[ 9 * 128 * 64];    // [stage][co][64]
__device__ __half g_wt2[18 * 128 * 64];
__device__ __half g_wt3[18 *  64 * 64];

__device__ __forceinline__ uint32_t smem_u32(const void* p) {
    uint32_t a;
    asm("{ .reg .u64 t; cvta.to.shared.u64 t, %1; cvt.u32.u64 %0, t; }"
        : "=r"(a) : "l"(p));
    return a;
}
// .cg: L2 -> smem, no L1 allocation (stage data is never re-read through L1)
__device__ __forceinline__ void cp16(uint32_t dst, const void* src) {
    asm volatile("cp.async.cg.shared.global [%0], [%1], 16;"
                 :: "r"(dst), "l"(src) : "memory");
}
#define CP_COMMIT() asm volatile("cp.async.commit_group;" ::: "memory")
#define CP_WAIT0()  asm volatile("cp.async.wait_group 0;"  ::: "memory")

__device__ __forceinline__ void ldm4(uint32_t* r, uint32_t addr) {
    asm volatile("ldmatrix.sync.aligned.m8n8.x4.shared.b16 {%0,%1,%2,%3}, [%4];"
                 : "=r"(r[0]), "=r"(r[1]), "=r"(r[2]), "=r"(r[3]) : "r"(addr));
}
__device__ __forceinline__ void ldm2(uint32_t* r, uint32_t addr) {
    asm volatile("ldmatrix.sync.aligned.m8n8.x2.shared.b16 {%0,%1}, [%2];"
                 : "=r"(r[0]), "=r"(r[1]) : "r"(addr));
}
__device__ __forceinline__ void mma16(float* d, const uint32_t* a, const uint32_t* b) {
    asm volatile(
        "mma.sync.aligned.m16n8k16.row.col.f32.f16.f16.f32 "
        "{%0,%1,%2,%3}, {%4,%5,%6,%7}, {%8,%9}, {%0,%1,%2,%3};"
        : "+f"(d[0]), "+f"(d[1]), "+f"(d[2]), "+f"(d[3])
        : "r"(a[0]), "r"(a[1]), "r"(a[2]), "r"(a[3]), "r"(b[0]), "r"(b[1]));
}

// ===========================================================================
// NWM m-warps x (8/NWM) n-warps; warp tile = (MT*16) co x NPW pix.
// MCTA = MT*16*NWM co ; NPIX = (8/NWM)*NPW pixels per CTA.
// ===========================================================================
template <int CIN, int MT, int NWM, int NPW, bool OUT_HALF, int OCC>
__global__ __launch_bounds__(256, OCC)
void conv_mma16(const __half* __restrict__ inPad,
                const __half* __restrict__ wt,
                void* __restrict__ outp)
{
    constexpr int G     = CIN / 32;
    constexpr int NS2   = 9 * G / 2;          // K64 stages
    constexpr int MCTA  = MT * 16 * NWM;
    constexpr int NPIX  = (8 / NWM) * NPW;
    constexpr int NT    = NPW / 8;
    constexpr int PITCH = 144;                // bytes per smem row (64 halfs + pad)
    constexpr int ABYTE = MCTA * PITCH;
    constexpr int BBYTE = NPIX * PITCH;
    constexpr int STAGE = ABYTE + BBYTE;
    constexpr int ASLOT = MCTA * 8;           // 16B copies per A fill (mult of 256)
    constexpr int BSLOT = NPIX * 8;
    constexpr int BIT   = (BSLOT + 255) / 256;

    extern __shared__ __align__(16) char smem[];
    const uint32_t sb = smem_u32(smem);

    const int tid = threadIdx.x;
    const int wid = tid >> 5, lid = tid & 31;
    const int g4  = lid >> 2, tg = lid & 3;
    const int tix = lid & 7, quad = lid >> 3;
    const int h = blockIdx.y, n = blockIdx.z;
    const int p0  = blockIdx.x * NPIX;
    const int mb  = (wid % NWM) * (MT * 16);
    const int nb  = (wid / NWM) * NPW;

    // per-thread ldmatrix offsets (within a stage)
    const uint32_t aOff = (uint32_t)((mb + (quad & 1) * 8 + tix) * PITCH + (quad >> 1) * 16);
    const uint32_t bOff = (uint32_t)(ABYTE + (nb + (quad >> 1) * 8 + tix) * PITCH + (quad & 1) * 16);

    const __half* src = inPad + (size_t)n * PADH * PADW * CIN;

    float acc[MT][NT][4];
#pragma unroll
    for (int m = 0; m < MT; m++)
#pragma unroll
        for (int nt = 0; nt < NT; nt++)
#pragma unroll
            for (int i = 0; i < 4; i++) acc[m][nt][i] = 0.0f;

    auto fillStage = [&](int s2) {
        const uint32_t st = sb + (s2 & 1) * STAGE;
        const __half* wsrc = wt + (size_t)s2 * (MCTA * 64);
#pragma unroll
        for (int it = 0; it * 256 < ASLOT; it++) {
            int slot = it * 256 + tid;
            int row = slot >> 3, q = slot & 7;
            cp16(st + (uint32_t)(row * PITCH + q * 16), wsrc + row * 64 + q * 8);
        }
        const int tap = (2 * s2) / G;
        const int g0  = (2 * s2) % G;
        const int kh  = tap / 3, kw = tap - kh * 3;
        const __half* base = src + ((size_t)(h + kh) * PADW + 3 + kw + p0) * CIN + g0 * 32;
#pragma unroll
        for (int it = 0; it < BIT; it++) {
            int slot = it * 256 + tid;
            if ((BSLOT % 256 == 0) || it < BIT - 1 || slot < BSLOT) {
                int pix = slot >> 3, q = slot & 7;
                cp16(st + ABYTE + (uint32_t)(pix * PITCH + q * 16),
                     base + (size_t)pix * CIN + q * 8);
            }
        }
        CP_COMMIT();
    };

    // prologue
    fillStage(0);

#pragma unroll 1
    for (int s2 = 0; s2 < NS2; s2++) {
        CP_WAIT0();
        __syncthreads();   // all warps done with stage s2-1 -> safe to refill
        if (s2 + 1 < NS2) fillStage(s2 + 1);

        const uint32_t st = sb + (s2 & 1) * STAGE;
        const uint32_t aB = st + aOff;
        const uint32_t bB = st + bOff;

#pragma unroll
        for (int ks = 0; ks < 4; ks++) {
            uint32_t a[MT][4];
#pragma unroll
            for (int m = 0; m < MT; m++)
                ldm4(a[m], aB + m * (16 * PITCH) + ks * 32);
            uint32_t b[NT][2];
#pragma unroll
            for (int pr = 0; pr < NT / 2; pr++) {
                uint32_t r4[4];
                ldm4(r4, bB + pr * (16 * PITCH) + ks * 32);
                b[2 * pr][0] = r4[0];     b[2 * pr][1] = r4[1];
                b[2 * pr + 1][0] = r4[2]; b[2 * pr + 1][1] = r4[3];
            }
            if (NT & 1)
                ldm2(b[NT - 1], bB + (NT / 2) * (16 * PITCH) + ks * 32);
#pragma unroll
            for (int m = 0; m < MT; m++)
#pragma unroll
                for (int nt = 0; nt < NT; nt++)
                    mma16(acc[m][nt], a[m], b[nt]);
        }
    }
    __syncthreads();                     // smem reuse below

    // ---- epilogue ----
    if (OUT_HALF) {
        __half* sOut = (__half*)smem;    // [NPIX pix][136]
#pragma unroll
        for (int m = 0; m < MT; m++) {
            int co = mb + m * 16 + g4;
#pragma unroll
            for (int nt = 0; nt < NT; nt++) {
                int pix = nb + nt * 8 + 2 * tg;
                sOut[(size_t)pix * 136 + co]           = __float2half_rn(acc[m][nt][0]);
                sOut[(size_t)(pix + 1) * 136 + co]     = __float2half_rn(acc[m][nt][1]);
                sOut[(size_t)pix * 136 + co + 8]       = __float2half_rn(acc[m][nt][2]);
                sOut[(size_t)(pix + 1) * 136 + co + 8] = __float2half_rn(acc[m][nt][3]);
            }
        }
        __syncthreads();
        __half* base = (__half*)outp
            + (((size_t)n * PADH + h + 1) * PADW + 4 + p0) * MCTA;
        for (int s = tid; s < NPIX * MCTA / 8; s += 256) {
            int pix = s / (MCTA / 8), q = s - pix * (MCTA / 8);
            *(uint4*)(base + (size_t)pix * MCTA + q * 8) =
                *(const uint4*)(sOut + (size_t)pix * 136 + q * 8);
        }
    } else {
        float* fo = (float*)outp;
#pragma unroll
        for (int m = 0; m < MT; m++) {
            int r0 = mb + m * 16 + g4;
#pragma unroll
            for (int nt = 0; nt < NT; nt++) {
                int col = p0 + nb + nt * 8 + 2 * tg;
                float* pA = fo + ((size_t)(n * MCTA + r0)     * HW + h) * HW + col;
                float* pB = fo + ((size_t)(n * MCTA + r0 + 8) * HW + h) * HW + col;
                *(float2*)pA = make_float2(acc[m][nt][0], acc[m][nt][1]);
                *(float2*)pB = make_float2(acc[m][nt][2], acc[m][nt][3]);
            }
        }
    }
}

// ===========================================================================
// single prep kernel: blocks [0, 3584) pad x ; blocks [3584, 3584+1152) repack
// all three weight tensors. Borders rely on zero-initialized device globals
// (validated in round 14: epilogues write interior only).
// ===========================================================================
#define PAD_BLOCKS (HW * NIMG)                       // 3584
#define WT_E1 (9 * 128 * 64)
#define WT_E2 (18 * 128 * 64)
#define WT_E3 (18 * 64 * 64)
#define WT_BLOCKS ((WT_E1 + WT_E2 + WT_E3) / 256)    // 1152

__global__ void prep_all(const float* __restrict__ x,
                         const float* __restrict__ w1,
                         const float* __restrict__ w2,
                         const float* __restrict__ w3)
{
    __shared__ __half sT[224 * 72];
    int bx = blockIdx.x;
    if (bx < PAD_BLOCKS) {
        int h = bx % HW, n = bx / HW;
        for (int idx = threadIdx.x; idx < 64 * 224; idx += 256) {
            int ci = idx / 224, w = idx - ci * 224;
            float v = x[(((size_t)n * 64 + ci) * HW + h) * HW + w];
            sT[w * 72 + ci] = __float2half_rn(v);
        }
        __syncthreads();
        __half* base = g_padX + (((size_t)n * PADH + h + 1) * PADW + 4) * 64;
        for (int s = threadIdx.x; s < 224 * 8; s += 256) {
            int w = s >> 3, q = s & 7;
            *(uint4*)(base + (size_t)w * 64 + q * 8) = *(const uint4*)(sT + w * 72 + q * 8);
        }
    } else {
        int i = (bx - PAD_BLOCKS) * 256 + threadIdx.x;
        const float* w; __half* wt; int CIN, MCTA, e;
        if (i < WT_E1)              { w = w1; wt = g_wt1; CIN = 64;  MCTA = 128; e = i; }
        else if (i < WT_E1 + WT_E2) { w = w2; wt = g_wt2; CIN = 128; MCTA = 128; e = i - WT_E1; }
        else                        { w = w3; wt = g_wt3; CIN = 128; MCTA = 64;  e = i - WT_E1 - WT_E2; }
        const int G = CIN / 32;
        int c64 = e & 63;
        int t   = e >> 6;
        int co  = t % MCTA;
        int s2  = t / MCTA;
        int tap = (2 * s2) / G;
        int ci  = ((2 * s2) % G) * 32 + c64;
        int kh  = tap / 3, kw = tap - kh * 3;
        wt[e] = __float2half_rn(w[((co * CIN + ci) * 3 + kh) * 3 + kw]);
    }
}

// ===========================================================================
extern "C" void kernel_launch(void* const* d_in, const int* in_sizes, int n_in,
                              void* d_out, int out_size)
{
    const float* x  = (const float*)d_in[0];
    const float* w1 = (const float*)d_in[1];
    const float* w2 = (const float*)d_in[2];
    const float* w3 = (const float*)d_in[3];
    float* out = (float*)d_out;

    __half *padX, *padB1, *padB2, *wt1, *wt2, *wt3;
    cudaGetSymbolAddress((void**)&padX,  g_padX);
    cudaGetSymbolAddress((void**)&padB1, g_padB1);
    cudaGetSymbolAddress((void**)&padB2, g_padB2);
    cudaGetSymbolAddress((void**)&wt1, g_wt1);
    cudaGetSymbolAddress((void**)&wt2, g_wt2);
    cudaGetSymbolAddress((void**)&wt3, g_wt3);

    constexpr int SM_12 = 2 * (128 * 144 + 112 * 144);   // 69120, 2 CTAs/SM
    constexpr int SM_3  = 2 * ( 64 * 144 + 224 * 144);   // 82944, 2 CTAs/SM
    cudaFuncSetAttribute(conv_mma16< 64, 2, 4, 56, true , 2>,
                         cudaFuncAttributeMaxDynamicSharedMemorySize, SM_12);
    cudaFuncSetAttribute(conv_mma16<128, 2, 4, 56, true , 2>,
                         cudaFuncAttributeMaxDynamicSharedMemorySize, SM_12);
    cudaFuncSetAttribute(conv_mma16<128, 2, 2, 56, false, 2>,
                         cudaFuncAttributeMaxDynamicSharedMemorySize, SM_3);

    // prep: ONE launch
    prep_all<<<PAD_BLOCKS + WT_BLOCKS, 256>>>(x, w1, w2, w3);

    dim3 block(256);
    dim3 grid12(2, HW, NIMG), grid3(1, HW, NIMG);
    conv_mma16< 64, 2, 4, 56, true , 2><<<grid12, block, SM_12>>>(padX,  wt1, padB1);
    conv_mma16<128, 2, 4, 56, true , 2><<<grid12, block, SM_12>>>(padB1, wt2, padB2);
    conv_mma16<128, 2, 2, 56, false, 2><<<grid3,  block, SM_3 >>>(padB2, wt3, out);
}

// round 17
// speedup vs baseline: 1.0162x; 1.0162x over previous
#include <cuda_runtime.h>
#include <cuda_fp16.h>
#include <cstdint>

// ===========================================================================
// 3x conv3x3 chain via mma.sync.m16n8k16 FP16 (fp32 accum), NHWC half
// intermediates. Round 17 = round-15 champion (measured best: 1364us),
// with ONE change: B fill issued before A fill (B is the long-latency
// L2/DRAM stream; A is an L1-resident weight re-read).
//  - cp.async .ca everywhere (L1 reuse of weights across CTAs and of input
//    rows across kh taps -- .cg regression in r16 proved this reuse is real).
//  - conv1/2: CTA = 128co x 112pix, 8 warps = 4(m) x 2(n), 2 CTAs/SM.
//  - conv3:   CTA =  64co x 224pix, 8 warps = 2(m) x 4(n), 2 CTAs/SM.
//  - K=64 stages (one tap x 64 contiguous ci), double buffer, one sync/stage,
//    pitch-144 conflict-free smem rows.
// N=16, H=W=224, 64 -> 128 -> 128 -> 64, fp32 NCHW in/out.
// ===========================================================================

#define HW     224
#define PADH   226
#define PADW   256
#define NIMG   16

__device__ __half g_padX [NIMG * PADH * PADW *  64];   // zero-init -> borders stay 0
__device__ __half g_padB1[NIMG * PADH * PADW * 128];
__device__ __half g_padB2[NIMG * PADH * PADW * 128];
__device__ __half g_wt1[ 9 * 128 * 64];    // [stage][co][64]
__device__ __half g_wt2[18 * 128 * 64];
__device__ __half g_wt3[18 *  64 * 64];

__device__ __forceinline__ uint32_t smem_u32(const void* p) {
    uint32_t a;
    asm("{ .reg .u64 t; cvta.to.shared.u64 t, %1; cvt.u32.u64 %0, t; }"
        : "=r"(a) : "l"(p));
    return a;
}
__device__ __forceinline__ void cp16(uint32_t dst, const void* src) {
    asm volatile("cp.async.ca.shared.global [%0], [%1], 16;"
                 :: "r"(dst), "l"(src) : "memory");
}
#define CP_COMMIT() asm volatile("cp.async.commit_group;" ::: "memory")
#define CP_WAIT0()  asm volatile("cp.async.wait_group 0;"  ::: "memory")

__device__ __forceinline__ void ldm4(uint32_t* r, uint32_t addr) {
    asm volatile("ldmatrix.sync.aligned.m8n8.x4.shared.b16 {%0,%1,%2,%3}, [%4];"
                 : "=r"(r[0]), "=r"(r[1]), "=r"(r[2]), "=r"(r[3]) : "r"(addr));
}
__device__ __forceinline__ void ldm2(uint32_t* r, uint32_t addr) {
    asm volatile("ldmatrix.sync.aligned.m8n8.x2.shared.b16 {%0,%1}, [%2];"
                 : "=r"(r[0]), "=r"(r[1]) : "r"(addr));
}
__device__ __forceinline__ void mma16(float* d, const uint32_t* a, const uint32_t* b) {
    asm volatile(
        "mma.sync.aligned.m16n8k16.row.col.f32.f16.f16.f32 "
        "{%0,%1,%2,%3}, {%4,%5,%6,%7}, {%8,%9}, {%0,%1,%2,%3};"
        : "+f"(d[0]), "+f"(d[1]), "+f"(d[2]), "+f"(d[3])
        : "r"(a[0]), "r"(a[1]), "r"(a[2]), "r"(a[3]), "r"(b[0]), "r"(b[1]));
}

// ===========================================================================
// NWM m-warps x (8/NWM) n-warps; warp tile = (MT*16) co x NPW pix.
// MCTA = MT*16*NWM co ; NPIX = (8/NWM)*NPW pixels per CTA.
// ===========================================================================
template <int CIN, int MT, int NWM, int NPW, bool OUT_HALF, int OCC>
__global__ __launch_bounds__(256, OCC)
void conv_mma16(const __half* __restrict__ inPad,
                const __half* __restrict__ wt,
                void* __restrict__ outp)
{
    constexpr int G     = CIN / 32;
    constexpr int NS2   = 9 * G / 2;          // K64 stages
    constexpr int MCTA  = MT * 16 * NWM;
    constexpr int NPIX  = (8 / NWM) * NPW;
    constexpr int NT    = NPW / 8;
    constexpr int PITCH = 144;                // bytes per smem row (64 halfs + pad)
    constexpr int ABYTE = MCTA * PITCH;
    constexpr int BBYTE = NPIX * PITCH;
    constexpr int STAGE = ABYTE + BBYTE;
    constexpr int ASLOT = MCTA * 8;           // 16B copies per A fill (mult of 256)
    constexpr int BSLOT = NPIX * 8;
    constexpr int BIT   = (BSLOT + 255) / 256;

    extern __shared__ __align__(16) char smem[];
    const uint32_t sb = smem_u32(smem);

    const int tid = threadIdx.x;
    const int wid = tid >> 5, lid = tid & 31;
    const int g4  = lid >> 2, tg = lid & 3;
    const int tix = lid & 7, quad = lid >> 3;
    const int h = blockIdx.y, n = blockIdx.z;
    const int p0  = blockIdx.x * NPIX;
    const int mb  = (wid % NWM) * (MT * 16);
    const int nb  = (wid / NWM) * NPW;

    // per-thread ldmatrix offsets (within a stage)
    const uint32_t aOff = (uint32_t)((mb + (quad & 1) * 8 + tix) * PITCH + (quad >> 1) * 16);
    const uint32_t bOff = (uint32_t)(ABYTE + (nb + (quad >> 1) * 8 + tix) * PITCH + (quad & 1) * 16);

    const __half* src = inPad + (size_t)n * PADH * PADW * CIN;

    float acc[MT][NT][4];
#pragma unroll
    for (int m = 0; m < MT; m++)
#pragma unroll
        for (int nt = 0; nt < NT; nt++)
#pragma unroll
            for (int i = 0; i < 4; i++) acc[m][nt][i] = 0.0f;

    auto fillStage = [&](int s2) {
        const uint32_t st = sb + (s2 & 1) * STAGE;
        // B first: the long-latency (L2/DRAM) stream starts earliest.
        const int tap = (2 * s2) / G;
        const int g0  = (2 * s2) % G;
        const int kh  = tap / 3, kw = tap - kh * 3;
        const __half* base = src + ((size_t)(h + kh) * PADW + 3 + kw + p0) * CIN + g0 * 32;
#pragma unroll
        for (int it = 0; it < BIT; it++) {
            int slot = it * 256 + tid;
            if ((BSLOT % 256 == 0) || it < BIT - 1 || slot < BSLOT) {
                int pix = slot >> 3, q = slot & 7;
                cp16(st + ABYTE + (uint32_t)(pix * PITCH + q * 16),
                     base + (size_t)pix * CIN + q * 8);
            }
        }
        // A second: weights are L1-resident (shared across CTAs), short latency.
        const __half* wsrc = wt + (size_t)s2 * (MCTA * 64);
#pragma unroll
        for (int it = 0; it * 256 < ASLOT; it++) {
            int slot = it * 256 + tid;
            int row = slot >> 3, q = slot & 7;
            cp16(st + (uint32_t)(row * PITCH + q * 16), wsrc + row * 64 + q * 8);
        }
        CP_COMMIT();
    };

    // prologue
    fillStage(0);

#pragma unroll 1
    for (int s2 = 0; s2 < NS2; s2++) {
        CP_WAIT0();
        __syncthreads();   // all warps done with stage s2-1 -> safe to refill
        if (s2 + 1 < NS2) fillStage(s2 + 1);

        const uint32_t st = sb + (s2 & 1) * STAGE;
        const uint32_t aB = st + aOff;
        const uint32_t bB = st + bOff;

#pragma unroll
        for (int ks = 0; ks < 4; ks++) {
            uint32_t a[MT][4];
#pragma unroll
            for (int m = 0; m < MT; m++)
                ldm4(a[m], aB + m * (16 * PITCH) + ks * 32);
            uint32_t b[NT][2];
#pragma unroll
            for (int pr = 0; pr < NT / 2; pr++) {
                uint32_t r4[4];
                ldm4(r4, bB + pr * (16 * PITCH) + ks * 32);
                b[2 * pr][0] = r4[0];     b[2 * pr][1] = r4[1];
                b[2 * pr + 1][0] = r4[2]; b[2 * pr + 1][1] = r4[3];
            }
            if (NT & 1)
                ldm2(b[NT - 1], bB + (NT / 2) * (16 * PITCH) + ks * 32);
#pragma unroll
            for (int m = 0; m < MT; m++)
#pragma unroll
                for (int nt = 0; nt < NT; nt++)
                    mma16(acc[m][nt], a[m], b[nt]);
        }
    }
    __syncthreads();                     // smem reuse below

    // ---- epilogue ----
    if (OUT_HALF) {
        __half* sOut = (__half*)smem;    // [NPIX pix][136]
#pragma unroll
        for (int m = 0; m < MT; m++) {
            int co = mb + m * 16 + g4;
#pragma unroll
            for (int nt = 0; nt < NT; nt++) {
                int pix = nb + nt * 8 + 2 * tg;
                sOut[(size_t)pix * 136 + co]           = __float2half_rn(acc[m][nt][0]);
                sOut[(size_t)(pix + 1) * 136 + co]     = __float2half_rn(acc[m][nt][1]);
                sOut[(size_t)pix * 136 + co + 8]       = __float2half_rn(acc[m][nt][2]);
                sOut[(size_t)(pix + 1) * 136 + co + 8] = __float2half_rn(acc[m][nt][3]);
            }
        }
        __syncthreads();
        __half* base = (__half*)outp
            + (((size_t)n * PADH + h + 1) * PADW + 4 + p0) * MCTA;
        for (int s = tid; s < NPIX * MCTA / 8; s += 256) {
            int pix = s / (MCTA / 8), q = s - pix * (MCTA / 8);
            *(uint4*)(base + (size_t)pix * MCTA + q * 8) =
                *(const uint4*)(sOut + (size_t)pix * 136 + q * 8);
        }
    } else {
        float* fo = (float*)outp;
#pragma unroll
        for (int m = 0; m < MT; m++) {
            int r0 = mb + m * 16 + g4;
#pragma unroll
            for (int nt = 0; nt < NT; nt++) {
                int col = p0 + nb + nt * 8 + 2 * tg;
                float* pA = fo + ((size_t)(n * MCTA + r0)     * HW + h) * HW + col;
                float* pB = fo + ((size_t)(n * MCTA + r0 + 8) * HW + h) * HW + col;
                *(float2*)pA = make_float2(acc[m][nt][0], acc[m][nt][1]);
                *(float2*)pB = make_float2(acc[m][nt][2], acc[m][nt][3]);
            }
        }
    }
}

// ===========================================================================
// prep kernels (r15 layout: 2 launches; no border zeroing -- device globals
// are zero-initialized and conv epilogues write interior only)
// ===========================================================================
__global__ void prep_pad_x(const float* __restrict__ x)
{
    __shared__ __half sT[224 * 72];
    int h = blockIdx.x, n = blockIdx.y;
    for (int idx = threadIdx.x; idx < 64 * 224; idx += 256) {
        int ci = idx / 224, w = idx - ci * 224;
        float v = x[(((size_t)n * 64 + ci) * HW + h) * HW + w];
        sT[w * 72 + ci] = __float2half_rn(v);
    }
    __syncthreads();
    __half* base = g_padX + (((size_t)n * PADH + h + 1) * PADW + 4) * 64;
    for (int s = threadIdx.x; s < 224 * 8; s += 256) {
        int w = s >> 3, q = s & 7;
        *(uint4*)(base + (size_t)w * 64 + q * 8) = *(const uint4*)(sT + w * 72 + q * 8);
    }
}

// One kernel repacks all three weight tensors ([stage][co][64] per region).
__global__ void prep_wt_all(const float* __restrict__ w1,
                            const float* __restrict__ w2,
                            const float* __restrict__ w3)
{
    const int E1 = 9 * 128 * 64, E2 = 18 * 128 * 64;
    int i = blockIdx.x * 256 + threadIdx.x;
    const float* w; __half* wt; int CIN, MCTA, e;
    if (i < E1)              { w = w1; wt = g_wt1; CIN = 64;  MCTA = 128; e = i; }
    else if (i < E1 + E2)    { w = w2; wt = g_wt2; CIN = 128; MCTA = 128; e = i - E1; }
    else                     { w = w3; wt = g_wt3; CIN = 128; MCTA = 64;  e = i - E1 - E2; }
    const int G = CIN / 32;
    int c64 = e & 63;
    int t   = e >> 6;
    int co  = t % MCTA;
    int s2  = t / MCTA;
    int tap = (2 * s2) / G;
    int ci  = ((2 * s2) % G) * 32 + c64;
    int kh  = tap / 3, kw = tap - kh * 3;
    wt[e] = __float2half_rn(w[((co * CIN + ci) * 3 + kh) * 3 + kw]);
}

// ===========================================================================
extern "C" void kernel_launch(void* const* d_in, const int* in_sizes, int n_in,
                              void* d_out, int out_size)
{
    const float* x  = (const float*)d_in[0];
    const float* w1 = (const float*)d_in[1];
    const float* w2 = (const float*)d_in[2];
    const float* w3 = (const float*)d_in[3];
    float* out = (float*)d_out;

    __half *padX, *padB1, *padB2, *wt1, *wt2, *wt3;
    cudaGetSymbolAddress((void**)&padX,  g_padX);
    cudaGetSymbolAddress((void**)&padB1, g_padB1);
    cudaGetSymbolAddress((void**)&padB2, g_padB2);
    cudaGetSymbolAddress((void**)&wt1, g_wt1);
    cudaGetSymbolAddress((void**)&wt2, g_wt2);
    cudaGetSymbolAddress((void**)&wt3, g_wt3);

    constexpr int SM_12 = 2 * (128 * 144 + 112 * 144);   // 69120, 2 CTAs/SM
    constexpr int SM_3  = 2 * ( 64 * 144 + 224 * 144);   // 82944, 2 CTAs/SM
    cudaFuncSetAttribute(conv_mma16< 64, 2, 4, 56, true , 2>,
                         cudaFuncAttributeMaxDynamicSharedMemorySize, SM_12);
    cudaFuncSetAttribute(conv_mma16<128, 2, 4, 56, true , 2>,
                         cudaFuncAttributeMaxDynamicSharedMemorySize, SM_12);
    cudaFuncSetAttribute(conv_mma16<128, 2, 2, 56, false, 2>,
                         cudaFuncAttributeMaxDynamicSharedMemorySize, SM_3);

    // prep: 2 launches (r15 layout)
    dim3 gpad(HW, NIMG);
    prep_pad_x<<<gpad, 256>>>(x);
    prep_wt_all<<<(9 * 128 * 64 + 18 * 128 * 64 + 18 * 64 * 64) / 256, 256>>>(w1, w2, w3);

    dim3 block(256);
    dim3 grid12(2, HW, NIMG), grid3(1, HW, NIMG);
    conv_mma16< 64, 2, 4, 56, true , 2><<<grid12, block, SM_12>>>(padX,  wt1, padB1);
    conv_mma16<128, 2, 4, 56, true , 2><<<grid12, block, SM_12>>>(padB1, wt2, padB2);
    conv_mma16<128, 2, 2, 56, false, 2><<<grid3,  block, SM_3 >>>(padB2, wt3, out);
}